// round 17
// baseline (speedup 1.0000x reference)
#include <cuda_runtime.h>
#include <cuda_fp16.h>
#include <cstdint>

// ExpectationSoftmaxLayer: s[b,o] = sum_i p*z, p = softmax(tau*z, i),
// z[b,o,i] = x[b,i] * leaky_clamp(w[o,i], 0, 1, 0.1)
//
// R17: q=1/2 f16x2-MUFU. Calibrated (R15/R16) linear error model:
// rel_err ~= 1.43e-3 * q  ->  q=1/2 gives ~7.1e-4 < 1e-3 gate.
// Slots s0,s1 of every float4 group go through one ex2.approx.f16x2
// (2 exps / 1 MUFU op); s2,s3 stay f32 ex2. All args, products and
// accumulation in f32 (table error dominates; keeps fma pipe light and
// DVFS clock high). MUFU bound: 6 cyc/warp-elem -> 85.2k cyc/SMSP.

#define B_    256
#define IN_   1024
#define OUT_  1024

#define RB_B  4
#define RB_O  2
#define WARPS 8
#define NSLAB (IN_ / 128)   // 8 slabs of 128 floats

#define LOG2E 1.4426950408889634f

__device__ float g_awk[OUT_ * IN_];

__device__ __forceinline__ float ex2f(float a) {
    float r;
    asm("ex2.approx.ftz.f32 %0, %1;" : "=f"(r) : "f"(a));
    return r;
}

__device__ __forceinline__ __half2 h2ex2(__half2 x) {
    uint32_t u = *reinterpret_cast<uint32_t*>(&x);
    uint32_t v;
    asm("ex2.approx.f16x2 %0, %1;" : "=r"(v) : "r"(u));
    return *reinterpret_cast<__half2*>(&v);
}

// leaky_clamp(x, 0, 1, 0.1) == 0.1*x + 0.9*saturate(x)
__device__ __forceinline__ float leaky_clamp01(float v) {
    return fmaf(0.9f, __saturatef(v), 0.1f * v);
}

__global__ __launch_bounds__(256)
void prep_awk_kernel(const float* __restrict__ w,
                     const float* __restrict__ log_tau) {
    const float k = expf(log_tau[0]) * LOG2E;
    int idx = (blockIdx.x * blockDim.x + threadIdx.x) * 4;
    float4 v = *reinterpret_cast<const float4*>(w + idx);
    float4 o;
    o.x = leaky_clamp01(v.x) * k;
    o.y = leaky_clamp01(v.y) * k;
    o.z = leaky_clamp01(v.z) * k;
    o.w = leaky_clamp01(v.w) * k;
    *reinterpret_cast<float4*>(g_awk + idx) = o;
}

__global__ __launch_bounds__(256, 4)
void esl_main_kernel(const float* __restrict__ x,
                     const float* __restrict__ log_tau,
                     float* __restrict__ out) {
    __shared__ float xs[RB_B][IN_];   // 16 KB

    const int tid  = threadIdx.x;
    const int lane = tid & 31;
    const int warp = tid >> 5;

    const int o0 = (blockIdx.x * WARPS + warp) * RB_O;
    const int b0 = blockIdx.y * RB_B;

    // Cooperative staging of the CTA's 4 x-rows.
    {
        const float4* __restrict__ src =
            reinterpret_cast<const float4*>(x + (size_t)b0 * IN_);
        float4* dst = reinterpret_cast<float4*>(&xs[0][0]);
#pragma unroll
        for (int t = tid; t < RB_B * IN_ / 4; t += 256)
            dst[t] = src[t];
    }
    __syncthreads();

    const float* __restrict__ arow = g_awk + (size_t)o0 * IN_ + lane * 4;

    float num[RB_B * RB_O];
    float den[RB_B * RB_O];
#pragma unroll
    for (int t = 0; t < RB_B * RB_O; t++) { num[t] = 0.f; den[t] = 0.f; }

    // Double-buffered awk slabs (1-slab register prefetch).
    float4 abuf[2][RB_O];
#pragma unroll
    for (int ro = 0; ro < RB_O; ro++)
        abuf[0][ro] = *reinterpret_cast<const float4*>(arow + ro * IN_);

    // One 128-wide slab for the 4x2 tile. Slots s0,s1 -> f16x2 exp (q = 1/2),
    // slots s2,s3 -> f32 exp.
#define ESL_BODY(ITG, PH)                                                     \
    do {                                                                      \
        const int ic_ = (ITG) * 128 + lane * 4;                               \
        const int icn_ = (((ITG) + 1) & (NSLAB - 1)) * 128;                   \
        _Pragma("unroll")                                                     \
        for (int ro = 0; ro < RB_O; ro++)                                     \
            abuf[((PH) + 1) & 1][ro] =                                        \
                *reinterpret_cast<const float4*>(arow + ro * IN_ + icn_);     \
        _Pragma("unroll")                                                     \
        for (int rb = 0; rb < RB_B; rb++) {                                   \
            float4 xv = *reinterpret_cast<const float4*>(&xs[rb][ic_]);       \
            _Pragma("unroll")                                                 \
            for (int ro = 0; ro < RB_O; ro++) {                               \
                float4 av = abuf[(PH) & 1][ro];                               \
                const int t = rb * RB_O + ro;                                 \
                float a0 = xv.x * av.x;                                       \
                float a1 = xv.y * av.y;                                       \
                float a2 = xv.z * av.z;                                       \
                float a3 = xv.w * av.w;                                       \
                __half2 ah = __floats2half2_rn(a0, a1);                       \
                float2 ef = __half22float2(h2ex2(ah));                        \
                float e0 = ef.x;                                              \
                float e1 = ef.y;                                              \
                float e2 = ex2f(a2);                                          \
                float e3 = ex2f(a3);                                          \
                den[t] += e0; num[t] = fmaf(a0, e0, num[t]);                  \
                den[t] += e1; num[t] = fmaf(a1, e1, num[t]);                  \
                den[t] += e2; num[t] = fmaf(a2, e2, num[t]);                  \
                den[t] += e3; num[t] = fmaf(a3, e3, num[t]);                  \
            }                                                                 \
        }                                                                     \
    } while (0)

#pragma unroll 1
    for (int ito = 0; ito < NSLAB / 2; ito++) {
        const int itg = ito * 2;
        ESL_BODY(itg + 0, 0);
        ESL_BODY(itg + 1, 1);
    }
#undef ESL_BODY

    const float inv_k = 1.0f / (expf(log_tau[0]) * LOG2E);

#pragma unroll
    for (int rb = 0; rb < RB_B; rb++) {
#pragma unroll
        for (int ro = 0; ro < RB_O; ro++) {
            const int t = rb * RB_O + ro;
            float n = num[t];
            float d = den[t];
#pragma unroll
            for (int off = 16; off > 0; off >>= 1) {
                n += __shfl_xor_sync(0xFFFFFFFFu, n, off);
                d += __shfl_xor_sync(0xFFFFFFFFu, d, off);
            }
            if (lane == 0) {
                out[(size_t)(b0 + rb) * OUT_ + (o0 + ro)] = (n / d) * inv_k;
            }
        }
    }
}

extern "C" void kernel_launch(void* const* d_in, const int* in_sizes, int n_in,
                              void* d_out, int out_size) {
    const float* x       = (const float*)d_in[0];  // (256, 1024)
    const float* weight  = (const float*)d_in[1];  // (1024, 1024)
    const float* log_tau = (const float*)d_in[2];  // scalar
    float* out           = (float*)d_out;          // (256, 1024)

    prep_awk_kernel<<<(OUT_ * IN_) / (256 * 4), 256>>>(weight, log_tau);

    dim3 grid(OUT_ / (WARPS * RB_O), B_ / RB_B);
    esl_main_kernel<<<grid, 256>>>(x, log_tau, out);
}